// round 7
// baseline (speedup 1.0000x reference)
#include <cuda_runtime.h>
#include <cuda_bf16.h>
#include <math.h>
#include <stdint.h>

#define B_ 64
#define T_ 30
#define S_ 31
#define E_ 128
#define U_ 256
#define V_ 32000

#define FC_K   768
#define FC_NS  24          // K stages of 32
#define CH_T   6           // timesteps per overlap chunk
#define CH_N   5           // number of chunks
#define CH_ROWS (CH_T * B_)   // 384

// ---------------- device scratch (no allocations allowed) ----------------
__device__ float g_keys[B_ * S_ * U_];
__device__ float g_xemb[B_ * T_ * E_];
__device__ float g_xw[B_ * T_ * 4 * U_];
__device__ float g_Wrc[2 * U_ * 4 * U_];
__device__ float g_hbuf[2][B_ * U_];
__device__ float g_c[B_ * U_];
__device__ float g_ctx[B_ * U_];
__device__ float g_hc[B_ * T_ * 2 * U_];      // t-major: row m = t*64+b
__device__ float g_attn[B_ * T_ * U_];        // t-major
__device__ __nv_bfloat16 g_Abf[B_ * T_ * FC_K];       // t-major [1920][768] hi|lo|hi
__device__ __nv_bfloat16 g_Wt[(size_t)V_ * FC_K];     // [32000][768] hi|hi|lo

__device__ __forceinline__ float sigm(float x) { return 1.0f / (1.0f + expf(-x)); }
__device__ __forceinline__ uint32_t smem_u32(const void* p) {
    return (uint32_t)__cvta_generic_to_shared(p);
}
__device__ __forceinline__ void cp16(uint32_t dst, const void* src) {
    asm volatile("cp.async.cg.shared.global [%0], [%1], 16;" :: "r"(dst), "l"(src));
}
__device__ __forceinline__ void ldm_x4(uint32_t* r, uint32_t addr) {
    asm volatile("ldmatrix.sync.aligned.m8n8.x4.shared.b16 {%0,%1,%2,%3}, [%4];"
                 : "=r"(r[0]), "=r"(r[1]), "=r"(r[2]), "=r"(r[3]) : "r"(addr));
}
__device__ __forceinline__ void mma16816(float* c, const uint32_t* a, uint32_t b0, uint32_t b1) {
    asm volatile(
        "mma.sync.aligned.m16n8k16.row.col.f32.bf16.bf16.f32 "
        "{%0,%1,%2,%3}, {%4,%5,%6,%7}, {%8,%9}, {%0,%1,%2,%3};"
        : "+f"(c[0]), "+f"(c[1]), "+f"(c[2]), "+f"(c[3])
        : "r"(a[0]), "r"(a[1]), "r"(a[2]), "r"(a[3]), "r"(b0), "r"(b1));
}

// ---------------- init ----------------
__global__ void k_init(const float* __restrict__ h0, const float* __restrict__ c0) {
    int i = blockIdx.x * blockDim.x + threadIdx.x;
    if (i < B_ * U_) {
        g_hbuf[0][i] = h0[i];
        g_c[i] = c0[i];
        g_ctx[i] = 0.0f;
    }
}

// ---------------- gather embeddings (int32/int64 autodetect) ----------------
__global__ void k_gather(const void* __restrict__ in_raw, const float* __restrict__ emb) {
    const int m = blockIdx.x;
    const int t = m >> 6;
    const int b = m & 63;
    const int* p32 = (const int*)in_raw;
    bool is64 = true;
#pragma unroll
    for (int i = 1; i <= 15; i += 2)
        if (p32[i] != 0) is64 = false;
    const int pos = b * T_ + t;
    long long idx = is64 ? ((const long long*)in_raw)[pos] : (long long)p32[pos];
    g_xemb[m * E_ + threadIdx.x] = emb[idx * E_ + threadIdx.x];
}

// ---------------- generic fp32 tiled SGEMM (small GEMMs only) ----------------
template <int BM, int BN, int BK, int TM, int TN>
__global__ __launch_bounds__(256) void sgemm_kernel(
    const float* __restrict__ A, const float* __restrict__ B,
    const float* __restrict__ bias, float* __restrict__ C,
    int M, int N, int K)
{
    constexpr int TX = BN / TN;
    __shared__ float As[BK][BM];
    __shared__ float Bs[BK][BN];
    const int tid = threadIdx.x;
    const int tx = tid % TX;
    const int ty = tid / TX;
    const int row0 = blockIdx.y * BM;
    const int col0 = blockIdx.x * BN;

    const int a_m = tid / (BK / 4);
    const int a_k = (tid % (BK / 4)) * 4;
    const int b_k = tid / (BN / 4);
    const int b_n = (tid % (BN / 4)) * 4;

    float acc[TM][TN];
#pragma unroll
    for (int i = 0; i < TM; i++)
#pragma unroll
        for (int j = 0; j < TN; j++) acc[i][j] = 0.0f;

    for (int k0 = 0; k0 < K; k0 += BK) {
        float4 av = *reinterpret_cast<const float4*>(&A[(size_t)(row0 + a_m) * K + k0 + a_k]);
        As[a_k + 0][a_m] = av.x;
        As[a_k + 1][a_m] = av.y;
        As[a_k + 2][a_m] = av.z;
        As[a_k + 3][a_m] = av.w;
        *reinterpret_cast<float4*>(&Bs[b_k][b_n]) =
            *reinterpret_cast<const float4*>(&B[(size_t)(k0 + b_k) * N + col0 + b_n]);
        __syncthreads();
#pragma unroll
        for (int k = 0; k < BK; k++) {
            float ra[TM], rb[TN];
#pragma unroll
            for (int i = 0; i < TM; i++) ra[i] = As[k][ty * TM + i];
#pragma unroll
            for (int j = 0; j < TN; j++) rb[j] = Bs[k][tx * TN + j];
#pragma unroll
            for (int i = 0; i < TM; i++)
#pragma unroll
                for (int j = 0; j < TN; j++) acc[i][j] += ra[i] * rb[j];
        }
        __syncthreads();
    }

    float bj[TN];
#pragma unroll
    for (int j = 0; j < TN; j++)
        bj[j] = bias ? bias[col0 + tx * TN + j] : 0.0f;

#pragma unroll
    for (int i = 0; i < TM; i++) {
        const size_t row = row0 + ty * TM + i;
#pragma unroll
        for (int j = 0; j < TN; j += 4) {
            float4 v;
            v.x = acc[i][j + 0] + bj[j + 0];
            v.y = acc[i][j + 1] + bj[j + 1];
            v.z = acc[i][j + 2] + bj[j + 2];
            v.w = acc[i][j + 3] + bj[j + 3];
            *reinterpret_cast<float4*>(&C[row * N + col0 + tx * TN + j]) = v;
        }
    }
}

__global__ void k_addWr(const float* __restrict__ Wr) {
    int i = blockIdx.x * blockDim.x + threadIdx.x;
    if (i < U_ * 4 * U_) g_Wrc[i] += Wr[i];
}

// ---------------- per-step: z GEMM + LSTM ----------------
__global__ __launch_bounds__(256) void step_a_kernel(
    int t, const float* __restrict__ Wr_in, int Kz)
{
    const int u0 = blockIdx.x * 2;
    const int tid = threadIdx.x;
    const int b = tid & 63;
    const int q = tid >> 6;
    const int ping = t & 1;
    const float* __restrict__ hprev = g_hbuf[ping];
    float* __restrict__ hnew = g_hbuf[1 - ping];
    const float* __restrict__ Wz = (Kz == 256) ? Wr_in : g_Wrc;

    __shared__ float As[32][65];
    __shared__ float2 Ws[32][4];
    __shared__ float zs[64][8];

    const float* xwt = g_xw + (size_t)(t * 64 + b) * 1024;
    const int j0 = q * 256 + u0;
    float acc0 = xwt[j0];
    float acc1 = xwt[j0 + 1];

    for (int k0 = 0; k0 < Kz; k0 += 32) {
#pragma unroll
        for (int r = 0; r < 2; r++) {
            int idx = tid + r * 256;
            int ab = idx >> 3;
            int kf = (idx & 7) * 4;
            int kg = k0 + kf;
            const float* src = (kg < 256) ? (hprev + ab * 256 + kg)
                                          : (g_ctx + ab * 256 + (kg - 256));
            float4 v = *reinterpret_cast<const float4*>(src);
            As[kf + 0][ab] = v.x;
            As[kf + 1][ab] = v.y;
            As[kf + 2][ab] = v.z;
            As[kf + 3][ab] = v.w;
        }
        {
            int k = tid >> 3;
            int c = tid & 7;
            int j = (c >> 1) * 256 + u0 + (c & 1);
            ((float*)Ws)[k * 8 + c] = Wz[(size_t)(k0 + k) * 1024 + j];
        }
        __syncthreads();
#pragma unroll
        for (int k = 0; k < 32; k++) {
            float a = As[k][b];
            float2 w = Ws[k][q];
            acc0 += a * w.x;
            acc1 += a * w.y;
        }
        __syncthreads();
    }

    zs[b][q * 2 + 0] = acc0;
    zs[b][q * 2 + 1] = acc1;
    __syncthreads();

    if (tid < 128) {
        int du = tid >> 6;
        int bb = tid & 63;
        int u = u0 + du;
        float zi = zs[bb][0 + du];
        float zf = zs[bb][2 + du];
        float zg = zs[bb][4 + du];
        float zo = zs[bb][6 + du];
        float cold = g_c[bb * 256 + u];
        float cn = sigm(zf) * cold + sigm(zi) * tanhf(zg);
        g_c[bb * 256 + u] = cn;
        float h = sigm(zo) * tanhf(cn);
        hnew[bb * 256 + u] = h;
        g_hc[(size_t)(t * 64 + bb) * 512 + u] = h;      // t-major
    }
}

// ---------------- per-step: attention ----------------
__global__ __launch_bounds__(256) void step_b_kernel(int t, const float* __restrict__ mem)
{
    const int b = blockIdx.x;
    const int tid = threadIdx.x;
    const int w = tid >> 5;
    const int l = tid & 31;
    const float* __restrict__ hcur = g_hbuf[1 - (t & 1)];

    __shared__ float hs[256];
    __shared__ float sc[32];
    __shared__ float al[32];

    hs[tid] = hcur[b * 256 + tid];
    __syncthreads();

    for (int s = w; s < S_; s += 8) {
        const float* kp = g_keys + (size_t)(b * S_ + s) * 256;
        float d = 0.0f;
#pragma unroll
        for (int i = 0; i < 8; i++) d += hs[l + 32 * i] * kp[l + 32 * i];
#pragma unroll
        for (int o = 16; o > 0; o >>= 1) d += __shfl_down_sync(0xffffffffu, d, o);
        if (l == 0) sc[s] = d;
    }
    __syncthreads();

    if (w == 0) {
        float v = (l < S_) ? sc[l] : -INFINITY;
        float mx = v;
#pragma unroll
        for (int o = 16; o > 0; o >>= 1) mx = fmaxf(mx, __shfl_xor_sync(0xffffffffu, mx, o));
        float e = (l < S_) ? expf(v - mx) : 0.0f;
        float sm = e;
#pragma unroll
        for (int o = 16; o > 0; o >>= 1) sm += __shfl_xor_sync(0xffffffffu, sm, o);
        if (l < S_) al[l] = e / sm;
    }
    __syncthreads();

    float c = 0.0f;
    const int u = tid;
#pragma unroll 1
    for (int s = 0; s < S_; s++)
        c += al[s] * mem[(size_t)(b * S_ + s) * 256 + u];
    g_ctx[b * 256 + u] = c;
    g_hc[(size_t)(t * 64 + b) * 512 + 256 + u] = c;     // t-major
}

// ---------------- A' conversion: attn f32 -> bf16 split [hi | lo | hi] ----------------
__global__ void k_convA(const float* __restrict__ attn, int row0) {
    const int m = row0 + blockIdx.x;
    const int k = threadIdx.x;
    float v = attn[(size_t)m * U_ + k];
    __nv_bfloat16 hi = __float2bfloat16(v);
    __nv_bfloat16 lo = __float2bfloat16(v - __bfloat162float(hi));
    size_t base = (size_t)m * FC_K + k;
    g_Abf[base] = hi;
    g_Abf[base + 256] = lo;
    g_Abf[base + 512] = hi;
}

// ---------------- W' conversion: W_fc [256][32000] -> Wt [32000][768] = [hi | hi | lo] ----------------
__global__ void k_convW(const float* __restrict__ W) {
    __shared__ float tile[32][33];
    const int n0 = blockIdx.x * 32;
    const int k0 = blockIdx.y * 32;
    const int tx = threadIdx.x;
    const int ty = threadIdx.y;   // 0..7
#pragma unroll
    for (int i = 0; i < 4; i++) {
        int k = ty + i * 8;
        tile[k][tx] = W[(size_t)(k0 + k) * V_ + n0 + tx];
    }
    __syncthreads();
#pragma unroll
    for (int i = 0; i < 4; i++) {
        int nr = ty + i * 8;
        float v = tile[tx][nr];
        __nv_bfloat16 hi = __float2bfloat16(v);
        __nv_bfloat16 lo = __float2bfloat16(v - __bfloat162float(hi));
        size_t base = (size_t)(n0 + nr) * FC_K + k0 + tx;
        g_Wt[base] = hi;
        g_Wt[base + 256] = hi;
        g_Wt[base + 512] = lo;
    }
}

// ---------------- HMMA FC GEMM chunk: rows [m_base, m_base+384) (t-major) ----------------
#define TILE_B   10240                 // 128 rows * 80B
#define BUF_B    (2 * TILE_B)          // A+B per buffer (20 KB)
__global__ __launch_bounds__(256, 2)
void fc_hmma_kernel(const __nv_bfloat16* __restrict__ Abf,
                    const __nv_bfloat16* __restrict__ Wt,
                    const float* __restrict__ bias,
                    float* __restrict__ out, int m_base)
{
    extern __shared__ char smem[];
    const uint32_t sbase = smem_u32(smem);
    const int tid = threadIdx.x;
    const int wid = tid >> 5;
    const int lane = tid & 31;
    const int n0 = blockIdx.x * 128;
    const int m0 = m_base + blockIdx.y * 128;

    const int warp_m = (wid >> 2) * 64;     // 0 or 64
    const int warp_nq = wid & 3;            // n quarter 0..3 -> n offset *32

    const char* Agl = (const char*)Abf + (size_t)m0 * (FC_K * 2);
    const char* Bgl = (const char*)Wt + (size_t)n0 * (FC_K * 2);

    float acc[4][4][4];
#pragma unroll
    for (int i = 0; i < 4; i++)
#pragma unroll
        for (int j = 0; j < 4; j++)
#pragma unroll
            for (int q = 0; q < 4; q++) acc[i][j][q] = 0.0f;

#define LOADST(S, P)                                                            \
    do {                                                                        \
        const uint32_t dA = sbase + (P) * BUF_B;                                \
        const uint32_t dB = dA + TILE_B;                                        \
        _Pragma("unroll")                                                       \
        for (int i_ = 0; i_ < 2; i_++) {                                        \
            int id_ = tid + i_ * 256;                                           \
            int r_ = id_ >> 2, c_ = id_ & 3;                                    \
            cp16(dA + r_ * 80 + c_ * 16,                                        \
                 Agl + (size_t)r_ * (FC_K * 2) + (S) * 64 + c_ * 16);           \
            cp16(dB + r_ * 80 + c_ * 16,                                        \
                 Bgl + (size_t)r_ * (FC_K * 2) + (S) * 64 + c_ * 16);           \
        }                                                                       \
        asm volatile("cp.async.commit_group;" ::: "memory");                    \
    } while (0)

    LOADST(0, 0);
    LOADST(1, 1);

    const uint32_t a_off = (uint32_t)((warp_m + (lane & 15)) * 80 + (lane >> 4) * 16);
    const uint32_t b_off = (uint32_t)((warp_nq * 32 + (lane >> 4) * 8 + (lane & 7)) * 80 +
                                      ((lane >> 3) & 1) * 16);

    for (int s = 0; s < FC_NS; s++) {
        if (s < FC_NS - 1)
            asm volatile("cp.async.wait_group 1;" ::: "memory");
        else
            asm volatile("cp.async.wait_group 0;" ::: "memory");
        __syncthreads();

        if (s + 2 < FC_NS) {
            const int pb = (s + 2) % 3;
            LOADST(s + 2, pb);
        }

        const uint32_t sA = sbase + (uint32_t)(s % 3) * BUF_B;
        const uint32_t sB = sA + TILE_B;
#pragma unroll
        for (int ks = 0; ks < 2; ks++) {
            uint32_t af[4][4];
#pragma unroll
            for (int mt = 0; mt < 4; mt++)
                ldm_x4(af[mt], sA + a_off + mt * (16 * 80) + ks * 32);
            uint32_t bf[2][4];
#pragma unroll
            for (int g = 0; g < 2; g++)
                ldm_x4(bf[g], sB + b_off + g * (16 * 80) + ks * 32);
#pragma unroll
            for (int mt = 0; mt < 4; mt++)
#pragma unroll
                for (int nt = 0; nt < 4; nt++)
                    mma16816(acc[mt][nt], af[mt],
                             bf[nt >> 1][(nt & 1) * 2], bf[nt >> 1][(nt & 1) * 2 + 1]);
        }
    }

    // ---- epilogue: regs -> SMEM -> coalesced STG + bias; remap t-major -> b-major rows ----
    float* ep = (float*)smem;
    const int myhalf = warp_nq >> 1;
    const int colq = (warp_nq & 1) * 32;

#pragma unroll 1
    for (int h = 0; h < 2; h++) {
        __syncthreads();
        if (myhalf == h) {
#pragma unroll
            for (int mt = 0; mt < 4; mt++)
#pragma unroll
                for (int nt = 0; nt < 4; nt++) {
                    int row = warp_m + mt * 16 + (lane >> 2);
                    int col = colq + nt * 8 + (lane & 3) * 2;
                    ep[row * 68 + col]            = acc[mt][nt][0];
                    ep[row * 68 + col + 1]        = acc[mt][nt][1];
                    ep[(row + 8) * 68 + col]      = acc[mt][nt][2];
                    ep[(row + 8) * 68 + col + 1]  = acc[mt][nt][3];
                }
        }
        __syncthreads();
        const int gn0 = n0 + h * 64;
#pragma unroll
        for (int i = 0; i < 8; i++) {
            int idx = tid + i * 256;
            int row = idx >> 4;
            int q = idx & 15;
            int gm = m0 + row;                         // t-major global row: t*64+b
            int orow = (gm & 63) * T_ + (gm >> 6);     // b*30+t
            float4 v = *(const float4*)&ep[row * 68 + q * 4];
            float4 bb = *(const float4*)&bias[gn0 + q * 4];
            v.x += bb.x; v.y += bb.y; v.z += bb.z; v.w += bb.w;
            *(float4*)&out[(size_t)orow * V_ + gn0 + q * 4] = v;
        }
    }
#undef LOADST
}

// ---------------- launcher ----------------
extern "C" void kernel_launch(void* const* d_in, const int* in_sizes, int n_in,
                              void* d_out, int out_size)
{
    const void*  inputs   = d_in[0];
    const float* memory   = (const float*)d_in[1];
    const float* sample_h = (const float*)d_in[2];
    const float* sample_c = (const float*)d_in[3];
    const float* emb      = (const float*)d_in[4];
    const float* W_k      = (const float*)d_in[5];
    const float* W_r      = (const float*)d_in[6];
    const float* b_lstm   = (const float*)d_in[7];
    const float* W_mem    = (const float*)d_in[8];
    const float* W_attn   = (const float*)d_in[9];
    const float* W_fc     = (const float*)d_in[10];
    const float* b_fc     = (const float*)d_in[11];
    float* out = (float*)d_out;

    float *p_keys, *p_xemb, *p_attn, *p_xw, *p_Wrc, *p_hc;
    __nv_bfloat16 *p_Abf, *p_Wt;
    cudaGetSymbolAddress((void**)&p_keys, g_keys);
    cudaGetSymbolAddress((void**)&p_xemb, g_xemb);
    cudaGetSymbolAddress((void**)&p_attn, g_attn);
    cudaGetSymbolAddress((void**)&p_Abf, g_Abf);
    cudaGetSymbolAddress((void**)&p_Wt, g_Wt);
    cudaGetSymbolAddress((void**)&p_xw, g_xw);
    cudaGetSymbolAddress((void**)&p_Wrc, g_Wrc);
    cudaGetSymbolAddress((void**)&p_hc, g_hc);

    // Fork stream + events: created fresh per host invocation (host code runs only
    // for correctness + capture, never on graph replay), intentionally not destroyed.
    cudaStream_t s2;
    cudaStreamCreateWithFlags(&s2, cudaStreamNonBlocking);
    cudaEvent_t ev[CH_N], evj;
    for (int c = 0; c < CH_N; c++) cudaEventCreateWithFlags(&ev[c], cudaEventDisableTiming);
    cudaEventCreateWithFlags(&evj, cudaEventDisableTiming);

    cudaFuncSetAttribute(fc_hmma_kernel, cudaFuncAttributeMaxDynamicSharedMemorySize, 3 * BUF_B);

    // W' split+transpose first (independent; must precede first FC chunk)
    k_convW<<<dim3(V_ / 32, U_ / 32), dim3(32, 8)>>>(W_fc);

    k_init<<<64, 256>>>(sample_h, sample_c);
    k_gather<<<B_ * T_, E_>>>(inputs, emb);
    sgemm_kernel<64, 64, 16, 4, 4><<<dim3(4, 31), 256>>>(memory, W_mem, nullptr, p_keys, 1984, 256, 256);
    sgemm_kernel<64, 64, 16, 4, 4><<<dim3(16, 30), 256>>>(p_xemb, W_k, b_lstm, p_xw, 1920, 1024, 128);
    sgemm_kernel<64, 64, 16, 4, 4><<<dim3(16, 8), 256>>>(W_attn, W_k + 128 * 1024, nullptr, p_Wrc, 512, 1024, 256);
    k_addWr<<<256, 1024>>>(W_r);

    for (int t = 0; t < T_; t++) {
        if (t == 0)
            step_a_kernel<<<128, 256>>>(t, W_r, 256);
        else
            step_a_kernel<<<128, 256>>>(t, W_r, 512);
        step_b_kernel<<<64, 256>>>(t, memory);

        if ((t + 1) % CH_T == 0) {
            const int c = t / CH_T;                 // chunk 0..4
            const int r0 = c * CH_ROWS;             // 384 rows per chunk (t-major)
            // attn chunk = hc[r0:r0+384] @ W_attn   (main stream: hc just produced)
            sgemm_kernel<64, 64, 16, 4, 4><<<dim3(4, CH_ROWS / 64), 256>>>(
                p_hc + (size_t)r0 * 512, W_attn, nullptr,
                p_attn + (size_t)r0 * 256, CH_ROWS, 256, 512);
            cudaEventRecord(ev[c], 0);
            // fork: convert + FC this chunk on s2 while recurrence continues
            cudaStreamWaitEvent(s2, ev[c], 0);
            k_convA<<<CH_ROWS, 256, 0, s2>>>(p_attn, r0);
            fc_hmma_kernel<<<dim3(V_ / 128, CH_ROWS / 128), 256, 3 * BUF_B, s2>>>(
                p_Abf, p_Wt, b_fc, out, r0);
        }
    }

    // join fork back into origin stream
    cudaEventRecord(evj, s2);
    cudaStreamWaitEvent(0, evj, 0);
}

// round 9
// speedup vs baseline: 1.2034x; 1.2034x over previous
#include <cuda_runtime.h>
#include <cuda_fp16.h>
#include <math.h>
#include <stdint.h>

#define B_ 64
#define T_ 30
#define S_ 31
#define E_ 128
#define U_ 256
#define V_ 32000

#define FC_K   512
#define FC_NS  16          // K stages of 32
#define NBLK   128

// ---------------- device scratch (no allocations allowed) ----------------
__device__ float g_keys[B_ * S_ * U_];
__device__ float g_xemb[B_ * T_ * E_];
__device__ float g_xw[B_ * T_ * 4 * U_];
__device__ float g_Wrc[2 * U_ * 4 * U_];
__device__ float g_hbuf[2][B_ * U_];
__device__ float g_ctx[B_ * U_];
__device__ float g_hc[B_ * T_ * 2 * U_];      // t-major: row m = t*64+b
__device__ float g_attn[B_ * T_ * U_];        // t-major
__device__ __half g_Abf[B_ * T_ * FC_K];      // t-major [1920][512]  a_hi | a_lo
__device__ __half g_Wt[(size_t)V_ * U_];      // [32000][256] w_hi (transposed W_fc)
__device__ unsigned g_bar;

__device__ __forceinline__ float sigm(float x) { return 1.0f / (1.0f + expf(-x)); }
__device__ __forceinline__ uint32_t smem_u32(const void* p) {
    return (uint32_t)__cvta_generic_to_shared(p);
}
__device__ __forceinline__ void cp16(uint32_t dst, const void* src) {
    asm volatile("cp.async.cg.shared.global [%0], [%1], 16;" :: "r"(dst), "l"(src));
}
__device__ __forceinline__ void ldm_x4(uint32_t* r, uint32_t addr) {
    asm volatile("ldmatrix.sync.aligned.m8n8.x4.shared.b16 {%0,%1,%2,%3}, [%4];"
                 : "=r"(r[0]), "=r"(r[1]), "=r"(r[2]), "=r"(r[3]) : "r"(addr));
}
__device__ __forceinline__ void mma16816(float* c, const uint32_t* a, uint32_t b0, uint32_t b1) {
    asm volatile(
        "mma.sync.aligned.m16n8k16.row.col.f32.f16.f16.f32 "
        "{%0,%1,%2,%3}, {%4,%5,%6,%7}, {%8,%9}, {%0,%1,%2,%3};"
        : "+f"(c[0]), "+f"(c[1]), "+f"(c[2]), "+f"(c[3])
        : "r"(a[0]), "r"(a[1]), "r"(a[2]), "r"(a[3]), "r"(b0), "r"(b1));
}

// software grid barrier: generation-counting, reset per launch by k_init
__device__ __forceinline__ void grid_barrier(unsigned target) {
    __threadfence();
    __syncthreads();
    if (threadIdx.x == 0) {
        atomicAdd(&g_bar, 1u);
        while (*((volatile unsigned*)&g_bar) < target) { }
        __threadfence();
    }
    __syncthreads();
}

// ---------------- init ----------------
__global__ void k_init(const float* __restrict__ h0) {
    int i = blockIdx.x * blockDim.x + threadIdx.x;
    if (i < B_ * U_) {
        g_hbuf[0][i] = h0[i];
        g_ctx[i] = 0.0f;
    }
    if (i == 0) g_bar = 0;
}

// ---------------- gather embeddings (int32/int64 autodetect) ----------------
__global__ void k_gather(const void* __restrict__ in_raw, const float* __restrict__ emb) {
    const int m = blockIdx.x;
    const int t = m >> 6;
    const int b = m & 63;
    const int* p32 = (const int*)in_raw;
    bool is64 = true;
#pragma unroll
    for (int i = 1; i <= 15; i += 2)
        if (p32[i] != 0) is64 = false;
    const int pos = b * T_ + t;
    long long idx = is64 ? ((const long long*)in_raw)[pos] : (long long)p32[pos];
    g_xemb[m * E_ + threadIdx.x] = emb[idx * E_ + threadIdx.x];
}

// ---------------- generic fp32 tiled SGEMM (small GEMMs only) ----------------
template <int BM, int BN, int BK, int TM, int TN>
__global__ __launch_bounds__(256) void sgemm_kernel(
    const float* __restrict__ A, const float* __restrict__ B,
    const float* __restrict__ bias, float* __restrict__ C,
    int M, int N, int K)
{
    constexpr int TX = BN / TN;
    __shared__ float As[BK][BM];
    __shared__ float Bs[BK][BN];
    const int tid = threadIdx.x;
    const int tx = tid % TX;
    const int ty = tid / TX;
    const int row0 = blockIdx.y * BM;
    const int col0 = blockIdx.x * BN;

    const int a_m = tid / (BK / 4);
    const int a_k = (tid % (BK / 4)) * 4;
    const int b_k = tid / (BN / 4);
    const int b_n = (tid % (BN / 4)) * 4;

    float acc[TM][TN];
#pragma unroll
    for (int i = 0; i < TM; i++)
#pragma unroll
        for (int j = 0; j < TN; j++) acc[i][j] = 0.0f;

    for (int k0 = 0; k0 < K; k0 += BK) {
        float4 av = *reinterpret_cast<const float4*>(&A[(size_t)(row0 + a_m) * K + k0 + a_k]);
        As[a_k + 0][a_m] = av.x;
        As[a_k + 1][a_m] = av.y;
        As[a_k + 2][a_m] = av.z;
        As[a_k + 3][a_m] = av.w;
        *reinterpret_cast<float4*>(&Bs[b_k][b_n]) =
            *reinterpret_cast<const float4*>(&B[(size_t)(k0 + b_k) * N + col0 + b_n]);
        __syncthreads();
#pragma unroll
        for (int k = 0; k < BK; k++) {
            float ra[TM], rb[TN];
#pragma unroll
            for (int i = 0; i < TM; i++) ra[i] = As[k][ty * TM + i];
#pragma unroll
            for (int j = 0; j < TN; j++) rb[j] = Bs[k][tx * TN + j];
#pragma unroll
            for (int i = 0; i < TM; i++)
#pragma unroll
                for (int j = 0; j < TN; j++) acc[i][j] += ra[i] * rb[j];
        }
        __syncthreads();
    }

    float bj[TN];
#pragma unroll
    for (int j = 0; j < TN; j++)
        bj[j] = bias ? bias[col0 + tx * TN + j] : 0.0f;

#pragma unroll
    for (int i = 0; i < TM; i++) {
        const size_t row = row0 + ty * TM + i;
#pragma unroll
        for (int j = 0; j < TN; j += 4) {
            float4 v;
            v.x = acc[i][j + 0] + bj[j + 0];
            v.y = acc[i][j + 1] + bj[j + 1];
            v.z = acc[i][j + 2] + bj[j + 2];
            v.w = acc[i][j + 3] + bj[j + 3];
            *reinterpret_cast<float4*>(&C[row * N + col0 + tx * TN + j]) = v;
        }
    }
}

__global__ void k_addWr(const float* __restrict__ Wr) {
    int i = blockIdx.x * blockDim.x + threadIdx.x;
    if (i < U_ * 4 * U_) g_Wrc[i] += Wr[i];
}

// ---------------- persistent recurrence: 30 steps, 1 launch ----------------
// 128 blocks, 256 threads. Per step:
//   phase A (all blocks): z = xw + [h,ctx] @ Wrc (t>0)  OR  z = xw + h @ W_r (t==0);
//                         LSTM elementwise (c in registers)
//   grid barrier
//   phase B (blocks 0..63): attention -> ctx
//   grid barrier
__global__ __launch_bounds__(256) void recur_kernel(
    const float* __restrict__ mem, const float* __restrict__ c0,
    const float* __restrict__ Wr)
{
    const int tid = threadIdx.x;
    const int blk = blockIdx.x;
    const int b = tid & 63;
    const int q = tid >> 6;
    const int u0 = blk * 2;

    __shared__ float2 Wc[512][4];     // 16 KB: this block's 8 Wrc columns
    __shared__ float2 WrS[256][4];    // 8 KB:  this block's 8 W_r columns (t==0 path)
    __shared__ float As[32][65];
    __shared__ float zs[64][8];
    __shared__ float hs[256];
    __shared__ float sc[32];
    __shared__ float al[32];

    // cache weight slices once
    for (int i = tid; i < 512 * 8; i += 256) {
        int k = i >> 3, c = i & 7;
        int j = (c >> 1) * 256 + u0 + (c & 1);
        ((float*)Wc)[k * 8 + c] = g_Wrc[(size_t)k * 1024 + j];
    }
    for (int i = tid; i < 256 * 8; i += 256) {
        int k = i >> 3, c = i & 7;
        int j = (c >> 1) * 256 + u0 + (c & 1);
        ((float*)WrS)[k * 8 + c] = Wr[(size_t)k * 1024 + j];
    }

    // c-state in registers: thread (tid<128) owns pair (bb=tid&63, u=u0+(tid>>6))
    float creg = 0.0f;
    if (tid < 128)
        creg = c0[(tid & 63) * 256 + u0 + (tid >> 6)];
    __syncthreads();

    unsigned gen = 0;
    for (int t = 0; t < T_; t++) {
        const float* __restrict__ hprev = g_hbuf[t & 1];
        float* __restrict__ hnew = g_hbuf[1 - (t & 1)];

        // ---- phase A ----
        const float* xwt = g_xw + (size_t)(t * 64 + b) * 1024;
        const int j0 = q * 256 + u0;
        float acc0 = xwt[j0];
        float acc1 = xwt[j0 + 1];

        // t==0: true attn_prev is ZERO (not [h0,0]@W_attn), so use plain W_r over h only.
        const int kmax = (t == 0) ? 256 : 512;
        const float2 (*Wp)[4] = (t == 0) ? WrS : Wc;

        for (int k0 = 0; k0 < kmax; k0 += 32) {
#pragma unroll
            for (int r = 0; r < 2; r++) {
                int idx = tid + r * 256;
                int ab = idx >> 3;
                int kf = (idx & 7) * 4;
                int kg = k0 + kf;
                const float4* src = (const float4*)((kg < 256)
                                        ? (hprev + ab * 256 + kg)
                                        : (g_ctx + ab * 256 + (kg - 256)));
                float4 v = __ldcg(src);        // L2 (cross-SM coherent) load
                As[kf + 0][ab] = v.x;
                As[kf + 1][ab] = v.y;
                As[kf + 2][ab] = v.z;
                As[kf + 3][ab] = v.w;
            }
            __syncthreads();
#pragma unroll
            for (int k = 0; k < 32; k++) {
                float a = As[k][b];
                float2 w = Wp[k0 + k][q];
                acc0 += a * w.x;
                acc1 += a * w.y;
            }
            __syncthreads();
        }
        zs[b][q * 2 + 0] = acc0;
        zs[b][q * 2 + 1] = acc1;
        __syncthreads();
        if (tid < 128) {
            int du = tid >> 6;
            int bb = tid & 63;
            int u = u0 + du;
            float zi = zs[bb][0 + du];
            float zf = zs[bb][2 + du];
            float zg = zs[bb][4 + du];
            float zo = zs[bb][6 + du];
            float cn = sigm(zf) * creg + sigm(zi) * tanhf(zg);
            creg = cn;
            float h = sigm(zo) * tanhf(cn);
            hnew[bb * 256 + u] = h;
            g_hc[(size_t)(t * 64 + bb) * 512 + u] = h;
        }
        gen++;
        grid_barrier(gen * NBLK);

        // ---- phase B: attention for batch blk (blocks 0..63) ----
        if (blk < 64) {
            const int bb = blk;
            const int w = tid >> 5;
            const int l = tid & 31;
            hs[tid] = __ldcg(hnew + bb * 256 + tid);
            __syncthreads();
            for (int s = w; s < S_; s += 8) {
                const float* kp = g_keys + (size_t)(bb * S_ + s) * 256;
                float d = 0.0f;
#pragma unroll
                for (int i = 0; i < 8; i++) d += hs[l + 32 * i] * kp[l + 32 * i];
#pragma unroll
                for (int o = 16; o > 0; o >>= 1) d += __shfl_down_sync(0xffffffffu, d, o);
                if (l == 0) sc[s] = d;
            }
            __syncthreads();
            if (w == 0) {
                float v = (l < S_) ? sc[l] : -INFINITY;
                float mx = v;
#pragma unroll
                for (int o = 16; o > 0; o >>= 1) mx = fmaxf(mx, __shfl_xor_sync(0xffffffffu, mx, o));
                float e = (l < S_) ? expf(v - mx) : 0.0f;
                float sm = e;
#pragma unroll
                for (int o = 16; o > 0; o >>= 1) sm += __shfl_xor_sync(0xffffffffu, sm, o);
                if (l < S_) al[l] = e / sm;
            }
            __syncthreads();
            float cx = 0.0f;
#pragma unroll 1
            for (int s = 0; s < S_; s++)
                cx += al[s] * mem[(size_t)(bb * S_ + s) * 256 + tid];
            g_ctx[bb * 256 + tid] = cx;
            g_hc[(size_t)(t * 64 + bb) * 512 + 256 + tid] = cx;
            __syncthreads();
        }
        gen++;
        grid_barrier(gen * NBLK);
    }
}

// ---------------- A' conversion: attn f32 -> fp16 split [hi | lo] ----------------
__global__ void k_convA(const float* __restrict__ attn) {
    const int m = blockIdx.x;
    const int k = threadIdx.x;
    float v = attn[(size_t)m * U_ + k];
    __half hi = __float2half_rn(v);
    __half lo = __float2half_rn(v - __half2float(hi));
    size_t base = (size_t)m * FC_K + k;
    g_Abf[base] = hi;
    g_Abf[base + 256] = lo;
}

// ---------------- W' conversion: W_fc [256][32000] -> Wt [32000][256] = w_hi ----------------
__global__ void k_convW(const float* __restrict__ W) {
    __shared__ float tile[32][33];
    const int n0 = blockIdx.x * 32;
    const int k0 = blockIdx.y * 32;
    const int tx = threadIdx.x;
    const int ty = threadIdx.y;   // 0..7
#pragma unroll
    for (int i = 0; i < 4; i++) {
        int k = ty + i * 8;
        tile[k][tx] = W[(size_t)(k0 + k) * V_ + n0 + tx];
    }
    __syncthreads();
#pragma unroll
    for (int i = 0; i < 4; i++) {
        int nr = ty + i * 8;
        float v = tile[tx][nr];
        g_Wt[(size_t)(n0 + nr) * U_ + k0 + tx] = __float2half_rn(v);
    }
}

// ---------------- HMMA FC GEMM: out = A'(1920x512 fp16) @ Wt^T(K-reuse) + b ----------------
// CTA 128x128, 8 warps of 64x32, BK=32, triple buffer, 2 CTA/SM.
// B stage s re-reads Wt cols (s%8)*32.. : logical W' = [w_hi | w_hi].
#define TILE_B   10240                 // 128 rows * 80B
#define BUF_B    (2 * TILE_B)
__global__ __launch_bounds__(256, 2)
void fc_hmma_kernel(const __half* __restrict__ Abf,
                    const __half* __restrict__ Wt,
                    const float* __restrict__ bias,
                    float* __restrict__ out)
{
    extern __shared__ char smem[];
    const uint32_t sbase = smem_u32(smem);
    const int tid = threadIdx.x;
    const int wid = tid >> 5;
    const int lane = tid & 31;
    const int n0 = blockIdx.x * 128;
    const int m0 = blockIdx.y * 128;

    const int warp_m = (wid >> 2) * 64;
    const int warp_nq = wid & 3;

    const char* Agl = (const char*)Abf + (size_t)m0 * (FC_K * 2);   // 1024 B rows
    const char* Bgl = (const char*)Wt + (size_t)n0 * (U_ * 2);      // 512 B rows

    float acc[4][4][4];
#pragma unroll
    for (int i = 0; i < 4; i++)
#pragma unroll
        for (int j = 0; j < 4; j++)
#pragma unroll
            for (int q = 0; q < 4; q++) acc[i][j][q] = 0.0f;

#define LOADST(S, P)                                                            \
    do {                                                                        \
        const uint32_t dA = sbase + (P) * BUF_B;                                \
        const uint32_t dB = dA + TILE_B;                                        \
        _Pragma("unroll")                                                       \
        for (int i_ = 0; i_ < 2; i_++) {                                        \
            int id_ = tid + i_ * 256;                                           \
            int r_ = id_ >> 2, c_ = id_ & 3;                                    \
            cp16(dA + r_ * 80 + c_ * 16,                                        \
                 Agl + (size_t)r_ * (FC_K * 2) + (S) * 64 + c_ * 16);           \
            cp16(dB + r_ * 80 + c_ * 16,                                        \
                 Bgl + (size_t)r_ * (U_ * 2) + ((S) & 7) * 64 + c_ * 16);       \
        }                                                                       \
        asm volatile("cp.async.commit_group;" ::: "memory");                    \
    } while (0)

    LOADST(0, 0);
    LOADST(1, 1);

    const uint32_t a_off = (uint32_t)((warp_m + (lane & 15)) * 80 + (lane >> 4) * 16);
    const uint32_t b_off = (uint32_t)((warp_nq * 32 + (lane >> 4) * 8 + (lane & 7)) * 80 +
                                      ((lane >> 3) & 1) * 16);

    for (int s = 0; s < FC_NS; s++) {
        if (s < FC_NS - 1)
            asm volatile("cp.async.wait_group 1;" ::: "memory");
        else
            asm volatile("cp.async.wait_group 0;" ::: "memory");
        __syncthreads();

        if (s + 2 < FC_NS) {
            const int pb = (s + 2) % 3;
            LOADST(s + 2, pb);
        }

        const uint32_t sA = sbase + (uint32_t)(s % 3) * BUF_B;
        const uint32_t sB = sA + TILE_B;
#pragma unroll
        for (int ks = 0; ks < 2; ks++) {
            uint32_t af[4][4];
#pragma unroll
            for (int mt = 0; mt < 4; mt++)
                ldm_x4(af[mt], sA + a_off + mt * (16 * 80) + ks * 32);
            uint32_t bf[2][4];
#pragma unroll
            for (int g = 0; g < 2; g++)
                ldm_x4(bf[g], sB + b_off + g * (16 * 80) + ks * 32);
#pragma unroll
            for (int mt = 0; mt < 4; mt++)
#pragma unroll
                for (int nt = 0; nt < 4; nt++)
                    mma16816(acc[mt][nt], af[mt],
                             bf[nt >> 1][(nt & 1) * 2], bf[nt >> 1][(nt & 1) * 2 + 1]);
        }
    }

    // ---- epilogue: regs -> SMEM -> coalesced STG + bias; t-major -> b-major remap ----
    float* ep = (float*)smem;
    const int myhalf = warp_nq >> 1;
    const int colq = (warp_nq & 1) * 32;

#pragma unroll 1
    for (int h = 0; h < 2; h++) {
        __syncthreads();
        if (myhalf == h) {
#pragma unroll
            for (int mt = 0; mt < 4; mt++)
#pragma unroll
                for (int nt = 0; nt < 4; nt++) {
                    int row = warp_m + mt * 16 + (lane >> 2);
                    int col = colq + nt * 8 + (lane & 3) * 2;
                    ep[row * 68 + col]            = acc[mt][nt][0];
                    ep[row * 68 + col + 1]        = acc[mt][nt][1];
                    ep[(row + 8) * 68 + col]      = acc[mt][nt][2];
                    ep[(row + 8) * 68 + col + 1]  = acc[mt][nt][3];
                }
        }
        __syncthreads();
        const int gn0 = n0 + h * 64;
#pragma unroll
        for (int i = 0; i < 8; i++) {
            int idx = tid + i * 256;
            int row = idx >> 4;
            int q = idx & 15;
            int gm = m0 + row;                         // t-major: t*64+b
            int orow = (gm & 63) * T_ + (gm >> 6);     // b*30+t
            float4 v = *(const float4*)&ep[row * 68 + q * 4];
            float4 bb = *(const float4*)&bias[gn0 + q * 4];
            v.x += bb.x; v.y += bb.y; v.z += bb.z; v.w += bb.w;
            *(float4*)&out[(size_t)orow * V_ + gn0 + q * 4] = v;
        }
    }
#undef LOADST
}

// ---------------- launcher ----------------
extern "C" void kernel_launch(void* const* d_in, const int* in_sizes, int n_in,
                              void* d_out, int out_size)
{
    const void*  inputs   = d_in[0];
    const float* memory   = (const float*)d_in[1];
    const float* sample_h = (const float*)d_in[2];
    const float* sample_c = (const float*)d_in[3];
    const float* emb      = (const float*)d_in[4];
    const float* W_k      = (const float*)d_in[5];
    const float* W_r      = (const float*)d_in[6];
    const float* b_lstm   = (const float*)d_in[7];
    const float* W_mem    = (const float*)d_in[8];
    const float* W_attn   = (const float*)d_in[9];
    const float* W_fc     = (const float*)d_in[10];
    const float* b_fc     = (const float*)d_in[11];
    float* out = (float*)d_out;

    float *p_keys, *p_xemb, *p_attn, *p_xw, *p_Wrc, *p_hc;
    __half *p_Abf, *p_Wt;
    cudaGetSymbolAddress((void**)&p_keys, g_keys);
    cudaGetSymbolAddress((void**)&p_xemb, g_xemb);
    cudaGetSymbolAddress((void**)&p_attn, g_attn);
    cudaGetSymbolAddress((void**)&p_Abf, g_Abf);
    cudaGetSymbolAddress((void**)&p_Wt, g_Wt);
    cudaGetSymbolAddress((void**)&p_xw, g_xw);
    cudaGetSymbolAddress((void**)&p_Wrc, g_Wrc);
    cudaGetSymbolAddress((void**)&p_hc, g_hc);

    cudaFuncSetAttribute(fc_hmma_kernel, cudaFuncAttributeMaxDynamicSharedMemorySize, 3 * BUF_B);

    // W' fp16 transpose (independent of recurrence)
    k_convW<<<dim3(V_ / 32, U_ / 32), dim3(32, 8)>>>(W_fc);

    k_init<<<64, 256>>>(sample_h);
    k_gather<<<B_ * T_, E_>>>(inputs, emb);
    sgemm_kernel<64, 64, 16, 4, 4><<<dim3(4, 31), 256>>>(memory, W_mem, nullptr, p_keys, 1984, 256, 256);
    sgemm_kernel<64, 64, 16, 4, 4><<<dim3(16, 30), 256>>>(p_xemb, W_k, b_lstm, p_xw, 1920, 1024, 128);
    sgemm_kernel<64, 64, 16, 4, 4><<<dim3(16, 8), 256>>>(W_attn, W_k + 128 * 1024, nullptr, p_Wrc, 512, 1024, 256);
    k_addWr<<<256, 1024>>>(W_r);

    // whole recurrence: ONE persistent launch (t=0 uses W_r path)
    recur_kernel<<<NBLK, 256>>>(memory, sample_c, W_r);

    // attn_seq = hc_seq @ W_attn (t-major rows)
    sgemm_kernel<64, 64, 16, 4, 4><<<dim3(4, 30), 256>>>(p_hc, W_attn, nullptr, p_attn, 1920, 256, 512);
    k_convA<<<B_ * T_, 256>>>(p_attn);

    // FC on tensor cores, fp16 2-term K=512 with W K-reuse
    fc_hmma_kernel<<<dim3(V_ / 128, 15), 256, 3 * BUF_B>>>(p_Abf, p_Wt, b_fc, out);
}

// round 11
// speedup vs baseline: 1.4356x; 1.1930x over previous
#include <cuda_runtime.h>
#include <cuda_fp16.h>
#include <math.h>
#include <stdint.h>

#define B_ 64
#define T_ 30
#define S_ 31
#define E_ 128
#define U_ 256
#define V_ 32000

#define FC_K   256
#define FC_NS  8           // K stages of 32
#define NBLK   128

// ---------------- device scratch (no allocations allowed) ----------------
__device__ float g_keys[B_ * S_ * U_];
__device__ float g_xemb[B_ * T_ * E_];
__device__ float g_xw[B_ * T_ * 4 * U_];
__device__ float g_Wrc[2 * U_ * 4 * U_];
__device__ float g_hbuf[2][B_ * U_];
__device__ float g_ctx[B_ * U_];
__device__ float g_hc[B_ * T_ * 2 * U_];      // t-major: row m = t*64+b
__device__ float g_attn[B_ * T_ * U_];        // t-major
__device__ __half g_Abf[B_ * T_ * FC_K];      // t-major [1920][256]  a_hi
__device__ __half g_Wt[(size_t)V_ * U_];      // [32000][256] w_hi (transposed W_fc)
__device__ unsigned g_bar;

__device__ __forceinline__ float sigm(float x) { return 1.0f / (1.0f + expf(-x)); }
__device__ __forceinline__ uint32_t smem_u32(const void* p) {
    return (uint32_t)__cvta_generic_to_shared(p);
}
__device__ __forceinline__ void cp16(uint32_t dst, const void* src) {
    asm volatile("cp.async.cg.shared.global [%0], [%1], 16;" :: "r"(dst), "l"(src));
}
__device__ __forceinline__ void ldm_x4(uint32_t* r, uint32_t addr) {
    asm volatile("ldmatrix.sync.aligned.m8n8.x4.shared.b16 {%0,%1,%2,%3}, [%4];"
                 : "=r"(r[0]), "=r"(r[1]), "=r"(r[2]), "=r"(r[3]) : "r"(addr));
}
__device__ __forceinline__ void mma16816(float* c, const uint32_t* a, uint32_t b0, uint32_t b1) {
    asm volatile(
        "mma.sync.aligned.m16n8k16.row.col.f32.f16.f16.f32 "
        "{%0,%1,%2,%3}, {%4,%5,%6,%7}, {%8,%9}, {%0,%1,%2,%3};"
        : "+f"(c[0]), "+f"(c[1]), "+f"(c[2]), "+f"(c[3])
        : "r"(a[0]), "r"(a[1]), "r"(a[2]), "r"(a[3]), "r"(b0), "r"(b1));
}

// software grid barrier: generation-counting, reset per launch by k_init
__device__ __forceinline__ void grid_barrier(unsigned target) {
    __threadfence();
    __syncthreads();
    if (threadIdx.x == 0) {
        atomicAdd(&g_bar, 1u);
        while (*((volatile unsigned*)&g_bar) < target) { }
        __threadfence();
    }
    __syncthreads();
}

// ---------------- init ----------------
__global__ void k_init(const float* __restrict__ h0) {
    int i = blockIdx.x * blockDim.x + threadIdx.x;
    if (i < B_ * U_) {
        g_hbuf[0][i] = h0[i];
        g_ctx[i] = 0.0f;
    }
    if (i == 0) g_bar = 0;
}

// ---------------- gather embeddings (int32/int64 autodetect) ----------------
__global__ void k_gather(const void* __restrict__ in_raw, const float* __restrict__ emb) {
    const int m = blockIdx.x;
    const int t = m >> 6;
    const int b = m & 63;
    const int* p32 = (const int*)in_raw;
    bool is64 = true;
#pragma unroll
    for (int i = 1; i <= 15; i += 2)
        if (p32[i] != 0) is64 = false;
    const int pos = b * T_ + t;
    long long idx = is64 ? ((const long long*)in_raw)[pos] : (long long)p32[pos];
    g_xemb[m * E_ + threadIdx.x] = emb[idx * E_ + threadIdx.x];
}

// ---------------- generic fp32 tiled SGEMM (small GEMMs only) ----------------
template <int BM, int BN, int BK, int TM, int TN>
__global__ __launch_bounds__(256) void sgemm_kernel(
    const float* __restrict__ A, const float* __restrict__ B,
    const float* __restrict__ bias, float* __restrict__ C,
    int M, int N, int K)
{
    constexpr int TX = BN / TN;
    __shared__ float As[BK][BM];
    __shared__ float Bs[BK][BN];
    const int tid = threadIdx.x;
    const int tx = tid % TX;
    const int ty = tid / TX;
    const int row0 = blockIdx.y * BM;
    const int col0 = blockIdx.x * BN;

    const int a_m = tid / (BK / 4);
    const int a_k = (tid % (BK / 4)) * 4;
    const int b_k = tid / (BN / 4);
    const int b_n = (tid % (BN / 4)) * 4;

    float acc[TM][TN];
#pragma unroll
    for (int i = 0; i < TM; i++)
#pragma unroll
        for (int j = 0; j < TN; j++) acc[i][j] = 0.0f;

    for (int k0 = 0; k0 < K; k0 += BK) {
        float4 av = *reinterpret_cast<const float4*>(&A[(size_t)(row0 + a_m) * K + k0 + a_k]);
        As[a_k + 0][a_m] = av.x;
        As[a_k + 1][a_m] = av.y;
        As[a_k + 2][a_m] = av.z;
        As[a_k + 3][a_m] = av.w;
        *reinterpret_cast<float4*>(&Bs[b_k][b_n]) =
            *reinterpret_cast<const float4*>(&B[(size_t)(k0 + b_k) * N + col0 + b_n]);
        __syncthreads();
#pragma unroll
        for (int k = 0; k < BK; k++) {
            float ra[TM], rb[TN];
#pragma unroll
            for (int i = 0; i < TM; i++) ra[i] = As[k][ty * TM + i];
#pragma unroll
            for (int j = 0; j < TN; j++) rb[j] = Bs[k][tx * TN + j];
#pragma unroll
            for (int i = 0; i < TM; i++)
#pragma unroll
                for (int j = 0; j < TN; j++) acc[i][j] += ra[i] * rb[j];
        }
        __syncthreads();
    }

    float bj[TN];
#pragma unroll
    for (int j = 0; j < TN; j++)
        bj[j] = bias ? bias[col0 + tx * TN + j] : 0.0f;

#pragma unroll
    for (int i = 0; i < TM; i++) {
        const size_t row = row0 + ty * TM + i;
#pragma unroll
        for (int j = 0; j < TN; j += 4) {
            float4 v;
            v.x = acc[i][j + 0] + bj[j + 0];
            v.y = acc[i][j + 1] + bj[j + 1];
            v.z = acc[i][j + 2] + bj[j + 2];
            v.w = acc[i][j + 3] + bj[j + 3];
            *reinterpret_cast<float4*>(&C[row * N + col0 + tx * TN + j]) = v;
        }
    }
}

__global__ void k_addWr(const float* __restrict__ Wr) {
    int i = blockIdx.x * blockDim.x + threadIdx.x;
    if (i < U_ * 4 * U_) g_Wrc[i] += Wr[i];
}

// ---------------- persistent recurrence: 30 steps, 1 launch ----------------
// Phase A double-buffers the activation tile: L2 loads for chunk k+1 are
// issued into registers before the sync/compute of chunk k.
__global__ __launch_bounds__(256) void recur_kernel(
    const float* __restrict__ mem, const float* __restrict__ c0,
    const float* __restrict__ Wr)
{
    const int tid = threadIdx.x;
    const int blk = blockIdx.x;
    const int b = tid & 63;
    const int q = tid >> 6;
    const int u0 = blk * 2;

    __shared__ float2 Wc[512][4];     // 16 KB
    __shared__ float2 WrS[256][4];    // 8 KB
    __shared__ float As[2][32][65];   // 16.6 KB double-buffered activation tile
    __shared__ float zs[64][8];
    __shared__ float hs[256];
    __shared__ float sc[32];
    __shared__ float al[32];

    for (int i = tid; i < 512 * 8; i += 256) {
        int k = i >> 3, c = i & 7;
        int j = (c >> 1) * 256 + u0 + (c & 1);
        ((float*)Wc)[k * 8 + c] = g_Wrc[(size_t)k * 1024 + j];
    }
    for (int i = tid; i < 256 * 8; i += 256) {
        int k = i >> 3, c = i & 7;
        int j = (c >> 1) * 256 + u0 + (c & 1);
        ((float*)WrS)[k * 8 + c] = Wr[(size_t)k * 1024 + j];
    }

    float creg = 0.0f;
    if (tid < 128)
        creg = c0[(tid & 63) * 256 + u0 + (tid >> 6)];
    __syncthreads();

    const int ab = tid >> 3;            // fixed per-thread load coords
    const int kf = (tid & 7) * 4;
    const int ab2 = (tid + 256) >> 3;
    const int kf2 = ((tid + 256) & 7) * 4;

    unsigned gen = 0;
    for (int t = 0; t < T_; t++) {
        const float* __restrict__ hprev = g_hbuf[t & 1];
        float* __restrict__ hnew = g_hbuf[1 - (t & 1)];

        const float* xwt = g_xw + (size_t)(t * 64 + b) * 1024;
        const int j0 = q * 256 + u0;
        float acc0 = xwt[j0];
        float acc1 = xwt[j0 + 1];

        // t==0: true attn_prev is ZERO, so use plain W_r over h only.
        const int kmax = (t == 0) ? 256 : 512;
        const float2 (*Wp)[4] = (t == 0) ? WrS : Wc;

        float4 va0, va1;
        {
            int kg1 = kf;
            const float4* s1 = (const float4*)((kg1 < 256)
                    ? (hprev + ab * 256 + kg1) : (g_ctx + ab * 256 + (kg1 - 256)));
            va0 = __ldcg(s1);
            int kg2 = kf2;
            const float4* s2 = (const float4*)((kg2 < 256)
                    ? (hprev + ab2 * 256 + kg2) : (g_ctx + ab2 * 256 + (kg2 - 256)));
            va1 = __ldcg(s2);
        }
        int buf = 0;
        for (int k0 = 0; k0 < kmax; k0 += 32) {
            // store current regs into As[buf]
            As[buf][kf + 0][ab] = va0.x;
            As[buf][kf + 1][ab] = va0.y;
            As[buf][kf + 2][ab] = va0.z;
            As[buf][kf + 3][ab] = va0.w;
            As[buf][kf2 + 0][ab2] = va1.x;
            As[buf][kf2 + 1][ab2] = va1.y;
            As[buf][kf2 + 2][ab2] = va1.z;
            As[buf][kf2 + 3][ab2] = va1.w;
            // issue next chunk's L2 loads early
            if (k0 + 32 < kmax) {
                int kg1 = k0 + 32 + kf;
                const float4* s1 = (const float4*)((kg1 < 256)
                        ? (hprev + ab * 256 + kg1) : (g_ctx + ab * 256 + (kg1 - 256)));
                va0 = __ldcg(s1);
                int kg2 = k0 + 32 + kf2;
                const float4* s2 = (const float4*)((kg2 < 256)
                        ? (hprev + ab2 * 256 + kg2) : (g_ctx + ab2 * 256 + (kg2 - 256)));
                va1 = __ldcg(s2);
            }
            __syncthreads();
#pragma unroll
            for (int k = 0; k < 32; k++) {
                float a = As[buf][k][b];
                float2 w = Wp[k0 + k][q];
                acc0 += a * w.x;
                acc1 += a * w.y;
            }
            buf ^= 1;
        }
        __syncthreads();
        zs[b][q * 2 + 0] = acc0;
        zs[b][q * 2 + 1] = acc1;
        __syncthreads();
        if (tid < 128) {
            int du = tid >> 6;
            int bb = tid & 63;
            int u = u0 + du;
            float zi = zs[bb][0 + du];
            float zf = zs[bb][2 + du];
            float zg = zs[bb][4 + du];
            float zo = zs[bb][6 + du];
            float cn = sigm(zf) * creg + sigm(zi) * tanhf(zg);
            creg = cn;
            float h = sigm(zo) * tanhf(cn);
            hnew[bb * 256 + u] = h;
            g_hc[(size_t)(t * 64 + bb) * 512 + u] = h;
        }
        gen++;
        grid_barrier(gen * NBLK);

        // ---- phase B: attention for batch blk (blocks 0..63) ----
        if (blk < 64) {
            const int bb = blk;
            const int w = tid >> 5;
            const int l = tid & 31;
            hs[tid] = __ldcg(hnew + bb * 256 + tid);
            __syncthreads();
            for (int s = w; s < S_; s += 8) {
                const float* kp = g_keys + (size_t)(bb * S_ + s) * 256;
                float d = 0.0f;
#pragma unroll
                for (int i = 0; i < 8; i++) d += hs[l + 32 * i] * kp[l + 32 * i];
#pragma unroll
                for (int o = 16; o > 0; o >>= 1) d += __shfl_down_sync(0xffffffffu, d, o);
                if (l == 0) sc[s] = d;
            }
            __syncthreads();
            if (w == 0) {
                float v = (l < S_) ? sc[l] : -INFINITY;
                float mx = v;
#pragma unroll
                for (int o = 16; o > 0; o >>= 1) mx = fmaxf(mx, __shfl_xor_sync(0xffffffffu, mx, o));
                float e = (l < S_) ? expf(v - mx) : 0.0f;
                float sm = e;
#pragma unroll
                for (int o = 16; o > 0; o >>= 1) sm += __shfl_xor_sync(0xffffffffu, sm, o);
                if (l < S_) al[l] = e / sm;
            }
            __syncthreads();
            float cx = 0.0f;
#pragma unroll 1
            for (int s = 0; s < S_; s++)
                cx += al[s] * mem[(size_t)(bb * S_ + s) * 256 + tid];
            g_ctx[bb * 256 + tid] = cx;
            g_hc[(size_t)(t * 64 + bb) * 512 + 256 + tid] = cx;
            __syncthreads();
        }
        gen++;
        grid_barrier(gen * NBLK);
    }
}

// ---------------- A' conversion: attn f32 -> fp16 (hi only) ----------------
__global__ void k_convA(const float* __restrict__ attn) {
    const int m = blockIdx.x;
    const int k = threadIdx.x;
    g_Abf[(size_t)m * FC_K + k] = __float2half_rn(attn[(size_t)m * U_ + k]);
}

// ---------------- W' conversion: W_fc [256][32000] -> Wt [32000][256] = w_hi ----------------
__global__ void k_convW(const float* __restrict__ W) {
    __shared__ float tile[32][33];
    const int n0 = blockIdx.x * 32;
    const int k0 = blockIdx.y * 32;
    const int tx = threadIdx.x;
    const int ty = threadIdx.y;   // 0..7
#pragma unroll
    for (int i = 0; i < 4; i++) {
        int k = ty + i * 8;
        tile[k][tx] = W[(size_t)(k0 + k) * V_ + n0 + tx];
    }
    __syncthreads();
#pragma unroll
    for (int i = 0; i < 4; i++) {
        int nr = ty + i * 8;
        float v = tile[tx][nr];
        g_Wt[(size_t)(n0 + nr) * U_ + k0 + tx] = __float2half_rn(v);
    }
}

// ---------------- HMMA FC GEMM: out = Ahi(1920x256) @ Wt^T + b ----------------
// CTA 128x128, 8 warps of 64x32, BK=32, triple buffer, 2 CTA/SM, 8 K-stages.
#define TILE_B   10240                 // 128 rows * 80B
#define BUF_B    (2 * TILE_B)
__global__ __launch_bounds__(256, 2)
void fc_hmma_kernel(const __half* __restrict__ Abf,
                    const __half* __restrict__ Wt,
                    const float* __restrict__ bias,
                    float* __restrict__ out)
{
    extern __shared__ char smem[];
    const uint32_t sbase = smem_u32(smem);
    const int tid = threadIdx.x;
    const int wid = tid >> 5;
    const int lane = tid & 31;
    const int n0 = blockIdx.x * 128;
    const int m0 = blockIdx.y * 128;

    const int warp_m = (wid >> 2) * 64;
    const int warp_nq = wid & 3;

    const char* Agl = (const char*)Abf + (size_t)m0 * (FC_K * 2);   // 512 B rows
    const char* Bgl = (const char*)Wt + (size_t)n0 * (U_ * 2);      // 512 B rows

    float acc[4][4][4];
#pragma unroll
    for (int i = 0; i < 4; i++)
#pragma unroll
        for (int j = 0; j < 4; j++)
#pragma unroll
            for (int q = 0; q < 4; q++) acc[i][j][q] = 0.0f;

#define LOADST(S, P)                                                            \
    do {                                                                        \
        const uint32_t dA = sbase + (P) * BUF_B;                                \
        const uint32_t dB = dA + TILE_B;                                        \
        _Pragma("unroll")                                                       \
        for (int i_ = 0; i_ < 2; i_++) {                                        \
            int id_ = tid + i_ * 256;                                           \
            int r_ = id_ >> 2, c_ = id_ & 3;                                    \
            cp16(dA + r_ * 80 + c_ * 16,                                        \
                 Agl + (size_t)r_ * (FC_K * 2) + (S) * 64 + c_ * 16);           \
            cp16(dB + r_ * 80 + c_ * 16,                                        \
                 Bgl + (size_t)r_ * (U_ * 2) + (S) * 64 + c_ * 16);             \
        }                                                                       \
        asm volatile("cp.async.commit_group;" ::: "memory");                    \
    } while (0)

    LOADST(0, 0);
    LOADST(1, 1);

    const uint32_t a_off = (uint32_t)((warp_m + (lane & 15)) * 80 + (lane >> 4) * 16);
    const uint32_t b_off = (uint32_t)((warp_nq * 32 + (lane >> 4) * 8 + (lane & 7)) * 80 +
                                      ((lane >> 3) & 1) * 16);

    for (int s = 0; s < FC_NS; s++) {
        if (s < FC_NS - 1)
            asm volatile("cp.async.wait_group 1;" ::: "memory");
        else
            asm volatile("cp.async.wait_group 0;" ::: "memory");
        __syncthreads();

        if (s + 2 < FC_NS) {
            const int pb = (s + 2) % 3;
            LOADST(s + 2, pb);
        }

        const uint32_t sA = sbase + (uint32_t)(s % 3) * BUF_B;
        const uint32_t sB = sA + TILE_B;
#pragma unroll
        for (int ks = 0; ks < 2; ks++) {
            uint32_t af[4][4];
#pragma unroll
            for (int mt = 0; mt < 4; mt++)
                ldm_x4(af[mt], sA + a_off + mt * (16 * 80) + ks * 32);
            uint32_t bf[2][4];
#pragma unroll
            for (int g = 0; g < 2; g++)
                ldm_x4(bf[g], sB + b_off + g * (16 * 80) + ks * 32);
#pragma unroll
            for (int mt = 0; mt < 4; mt++)
#pragma unroll
                for (int nt = 0; nt < 4; nt++)
                    mma16816(acc[mt][nt], af[mt],
                             bf[nt >> 1][(nt & 1) * 2], bf[nt >> 1][(nt & 1) * 2 + 1]);
        }
    }

    // ---- epilogue: regs -> SMEM -> coalesced STG + bias; t-major -> b-major remap ----
    float* ep = (float*)smem;
    const int myhalf = warp_nq >> 1;
    const int colq = (warp_nq & 1) * 32;

#pragma unroll 1
    for (int h = 0; h < 2; h++) {
        __syncthreads();
        if (myhalf == h) {
#pragma unroll
            for (int mt = 0; mt < 4; mt++)
#pragma unroll
                for (int nt = 0; nt < 4; nt++) {
                    int row = warp_m + mt * 16 + (lane >> 2);
                    int col = colq + nt * 8 + (lane & 3) * 2;
                    ep[row * 68 + col]            = acc[mt][nt][0];
                    ep[row * 68 + col + 1]        = acc[mt][nt][1];
                    ep[(row + 8) * 68 + col]      = acc[mt][nt][2];
                    ep[(row + 8) * 68 + col + 1]  = acc[mt][nt][3];
                }
        }
        __syncthreads();
        const int gn0 = n0 + h * 64;
#pragma unroll
        for (int i = 0; i < 8; i++) {
            int idx = tid + i * 256;
            int row = idx >> 4;
            int q = idx & 15;
            int gm = m0 + row;                         // t-major: t*64+b
            int orow = (gm & 63) * T_ + (gm >> 6);     // b*30+t
            float4 v = *(const float4*)&ep[row * 68 + q * 4];
            float4 bb = *(const float4*)&bias[gn0 + q * 4];
            v.x += bb.x; v.y += bb.y; v.z += bb.z; v.w += bb.w;
            *(float4*)&out[(size_t)orow * V_ + gn0 + q * 4] = v;
        }
    }
#undef LOADST
}

// ---------------- launcher ----------------
extern "C" void kernel_launch(void* const* d_in, const int* in_sizes, int n_in,
                              void* d_out, int out_size)
{
    const void*  inputs   = d_in[0];
    const float* memory   = (const float*)d_in[1];
    const float* sample_h = (const float*)d_in[2];
    const float* sample_c = (const float*)d_in[3];
    const float* emb      = (const float*)d_in[4];
    const float* W_k      = (const float*)d_in[5];
    const float* W_r      = (const float*)d_in[6];
    const float* b_lstm   = (const float*)d_in[7];
    const float* W_mem    = (const float*)d_in[8];
    const float* W_attn   = (const float*)d_in[9];
    const float* W_fc     = (const float*)d_in[10];
    const float* b_fc     = (const float*)d_in[11];
    float* out = (float*)d_out;

    float *p_keys, *p_xemb, *p_attn, *p_xw, *p_Wrc, *p_hc;
    __half *p_Abf, *p_Wt;
    cudaGetSymbolAddress((void**)&p_keys, g_keys);
    cudaGetSymbolAddress((void**)&p_xemb, g_xemb);
    cudaGetSymbolAddress((void**)&p_attn, g_attn);
    cudaGetSymbolAddress((void**)&p_Abf, g_Abf);
    cudaGetSymbolAddress((void**)&p_Wt, g_Wt);
    cudaGetSymbolAddress((void**)&p_xw, g_xw);
    cudaGetSymbolAddress((void**)&p_Wrc, g_Wrc);
    cudaGetSymbolAddress((void**)&p_hc, g_hc);

    cudaFuncSetAttribute(fc_hmma_kernel, cudaFuncAttributeMaxDynamicSharedMemorySize, 3 * BUF_B);

    // W' fp16 transpose (independent of recurrence)
    k_convW<<<dim3(V_ / 32, U_ / 32), dim3(32, 8)>>>(W_fc);

    k_init<<<64, 256>>>(sample_h);
    k_gather<<<B_ * T_, E_>>>(inputs, emb);
    sgemm_kernel<64, 64, 16, 4, 4><<<dim3(4, 31), 256>>>(memory, W_mem, nullptr, p_keys, 1984, 256, 256);
    sgemm_kernel<64, 64, 16, 4, 4><<<dim3(16, 30), 256>>>(p_xemb, W_k, b_lstm, p_xw, 1920, 1024, 128);
    sgemm_kernel<64, 64, 16, 4, 4><<<dim3(16, 8), 256>>>(W_attn, W_k + 128 * 1024, nullptr, p_Wrc, 512, 1024, 256);
    k_addWr<<<256, 1024>>>(W_r);

    // whole recurrence: ONE persistent launch (t=0 uses W_r path)
    recur_kernel<<<NBLK, 256>>>(memory, sample_c, W_r);

    // attn_seq = hc_seq @ W_attn (t-major rows)
    sgemm_kernel<64, 64, 16, 4, 4><<<dim3(4, 30), 256>>>(p_hc, W_attn, nullptr, p_attn, 1920, 256, 512);
    k_convA<<<B_ * T_, 256>>>(p_attn);

    // FC on tensor cores, single-term fp16 K=256
    fc_hmma_kernel<<<dim3(V_ / 128, 15), 256, 3 * BUF_B>>>(p_Abf, p_Wt, b_fc, out);
}

// round 12
// speedup vs baseline: 1.9545x; 1.3615x over previous
#include <cuda_runtime.h>
#include <cuda_fp16.h>
#include <math.h>
#include <stdint.h>

#define B_ 64
#define T_ 30
#define S_ 31
#define E_ 128
#define U_ 256
#define V_ 32000

#define FC_K   256
#define FC_NS  8           // K stages of 32
#define NBLK   128

// ---------------- device scratch (no allocations allowed) ----------------
__device__ float g_keys[B_ * S_ * U_];
__device__ float g_xemb[B_ * T_ * E_];
__device__ float g_xw[B_ * T_ * 4 * U_];
__device__ float g_Wrc[2 * U_ * 4 * U_];
__device__ float g_hbuf[2][B_ * U_];
__device__ float g_ctx[B_ * U_];
__device__ float g_hc[B_ * T_ * 2 * U_];      // t-major: row m = t*64+b
__device__ float g_attn[B_ * T_ * U_];        // t-major
__device__ __half g_Abf[B_ * T_ * FC_K];      // t-major [1920][256]  a_hi
__device__ __half g_Wt[(size_t)V_ * U_];      // [32000][256] w_hi (transposed W_fc)
__device__ unsigned g_bar;

__device__ __forceinline__ float sigm(float x) { return 1.0f / (1.0f + expf(-x)); }
__device__ __forceinline__ uint32_t smem_u32(const void* p) {
    return (uint32_t)__cvta_generic_to_shared(p);
}
__device__ __forceinline__ void cp16(uint32_t dst, const void* src) {
    asm volatile("cp.async.cg.shared.global [%0], [%1], 16;" :: "r"(dst), "l"(src));
}
__device__ __forceinline__ void ldm_x4(uint32_t* r, uint32_t addr) {
    asm volatile("ldmatrix.sync.aligned.m8n8.x4.shared.b16 {%0,%1,%2,%3}, [%4];"
                 : "=r"(r[0]), "=r"(r[1]), "=r"(r[2]), "=r"(r[3]) : "r"(addr));
}
__device__ __forceinline__ void mma16816(float* c, const uint32_t* a, uint32_t b0, uint32_t b1) {
    asm volatile(
        "mma.sync.aligned.m16n8k16.row.col.f32.f16.f16.f32 "
        "{%0,%1,%2,%3}, {%4,%5,%6,%7}, {%8,%9}, {%0,%1,%2,%3};"
        : "+f"(c[0]), "+f"(c[1]), "+f"(c[2]), "+f"(c[3])
        : "r"(a[0]), "r"(a[1]), "r"(a[2]), "r"(a[3]), "r"(b0), "r"(b1));
}

// software grid barrier: generation-counting, reset per launch by gather-init
__device__ __forceinline__ void grid_barrier(unsigned target) {
    __threadfence();
    __syncthreads();
    if (threadIdx.x == 0) {
        atomicAdd(&g_bar, 1u);
        while (*((volatile unsigned*)&g_bar) < target) { }
        __threadfence();
    }
    __syncthreads();
}

// ---------------- gather embeddings + fused state init ----------------
__global__ void k_gather(const void* __restrict__ in_raw, const float* __restrict__ emb,
                         const float* __restrict__ h0) {
    const int m = blockIdx.x;
    const int t = m >> 6;
    const int b = m & 63;
    const int* p32 = (const int*)in_raw;
    bool is64 = true;
#pragma unroll
    for (int i = 1; i <= 15; i += 2)
        if (p32[i] != 0) is64 = false;
    const int pos = b * T_ + t;
    long long idx = is64 ? ((const long long*)in_raw)[pos] : (long long)p32[pos];
    g_xemb[m * E_ + threadIdx.x] = emb[idx * E_ + threadIdx.x];

    // fused init: blocks 0..63 initialize h/ctx (2 elems per thread), block 0 resets barrier
    if (m < 64) {
        int i = m * 256 + threadIdx.x * 2;
        g_hbuf[0][i]     = h0[i];
        g_hbuf[0][i + 1] = h0[i + 1];
        g_ctx[i]     = 0.0f;
        g_ctx[i + 1] = 0.0f;
        if (m == 0 && threadIdx.x == 0) g_bar = 0;
    }
}

// ---------------- shared fp32 GEMM body (64x64 tile, BK=16, 4x4 per thread) ----------------
__device__ __forceinline__ void sgemm_dev(
    const float* __restrict__ A, const float* __restrict__ B,
    const float* __restrict__ bias, const float* __restrict__ addm,
    float* __restrict__ C, int M, int N, int K, int bx, int by)
{
    __shared__ float As[16][64];
    __shared__ float Bs[16][64];
    const int tid = threadIdx.x;
    const int tx = tid % 16;
    const int ty = tid / 16;
    const int row0 = by * 64;
    const int col0 = bx * 64;

    const int a_m = tid / 4;
    const int a_k = (tid % 4) * 4;
    const int b_k = tid / 16;
    const int b_n = (tid % 16) * 4;

    float acc[4][4];
#pragma unroll
    for (int i = 0; i < 4; i++)
#pragma unroll
        for (int j = 0; j < 4; j++) acc[i][j] = 0.0f;

    for (int k0 = 0; k0 < K; k0 += 16) {
        float4 av = *reinterpret_cast<const float4*>(&A[(size_t)(row0 + a_m) * K + k0 + a_k]);
        As[a_k + 0][a_m] = av.x;
        As[a_k + 1][a_m] = av.y;
        As[a_k + 2][a_m] = av.z;
        As[a_k + 3][a_m] = av.w;
        *reinterpret_cast<float4*>(&Bs[b_k][b_n]) =
            *reinterpret_cast<const float4*>(&B[(size_t)(k0 + b_k) * N + col0 + b_n]);
        __syncthreads();
#pragma unroll
        for (int k = 0; k < 16; k++) {
            float ra[4], rb[4];
#pragma unroll
            for (int i = 0; i < 4; i++) ra[i] = As[k][ty * 4 + i];
#pragma unroll
            for (int j = 0; j < 4; j++) rb[j] = Bs[k][tx * 4 + j];
#pragma unroll
            for (int i = 0; i < 4; i++)
#pragma unroll
                for (int j = 0; j < 4; j++) acc[i][j] += ra[i] * rb[j];
        }
        __syncthreads();
    }

    float bj[4];
#pragma unroll
    for (int j = 0; j < 4; j++)
        bj[j] = bias ? bias[col0 + tx * 4 + j] : 0.0f;

#pragma unroll
    for (int i = 0; i < 4; i++) {
        const size_t row = row0 + ty * 4 + i;
        float4 v;
        v.x = acc[i][0] + bj[0];
        v.y = acc[i][1] + bj[1];
        v.z = acc[i][2] + bj[2];
        v.w = acc[i][3] + bj[3];
        if (addm) {
            float4 am = *reinterpret_cast<const float4*>(&addm[row * N + col0 + tx * 4]);
            v.x += am.x; v.y += am.y; v.z += am.z; v.w += am.w;
        }
        *reinterpret_cast<float4*>(&C[row * N + col0 + tx * 4]) = v;
    }
}

// ---------------- fused pre-GEMMs: keys | xw | Wcomb(+W_r) in one launch ----------------
__global__ __launch_bounds__(256) void k_multigemm(
    const float* __restrict__ memory, const float* __restrict__ W_mem,
    const float* __restrict__ W_k, const float* __restrict__ b_lstm,
    const float* __restrict__ W_attn, const float* __restrict__ W_r)
{
    const int bid = blockIdx.x;
    if (bid < 124) {
        // keys[1984,256] = memory @ W_mem
        sgemm_dev(memory, W_mem, nullptr, nullptr, g_keys, 1984, 256, 256, bid % 4, bid / 4);
    } else if (bid < 604) {
        // xw[1920,1024] = xemb @ W_k[:128] + b_lstm
        int r = bid - 124;
        sgemm_dev(g_xemb, W_k, b_lstm, nullptr, g_xw, 1920, 1024, 128, r % 16, r / 16);
    } else {
        // Wrc[512,1024] = W_attn @ W_k[128:] + [W_r ; 0]
        int r = bid - 604;
        int by = r / 16;
        const float* addm = (by < 4) ? W_r : nullptr;   // W_r covers rows 0..255 only
        // addm indexing inside sgemm_dev uses absolute row*N; W_r is [256][1024] so
        // rows 0..255 align exactly. Rows >= 256 pass nullptr.
        sgemm_dev(W_attn, W_k + 128 * 1024, nullptr, addm, g_Wrc, 512, 1024, 256, r % 16, by);
    }
}

// ---------------- attn projection wrapper ----------------
__global__ __launch_bounds__(256) void k_sgemm_attn(const float* __restrict__ Wa) {
    sgemm_dev(g_hc, Wa, nullptr, nullptr, g_attn, 1920, 256, 512, blockIdx.x, blockIdx.y);
}

// ---------------- persistent recurrence: 30 steps, 1 launch ----------------
__global__ __launch_bounds__(256) void recur_kernel(
    const float* __restrict__ mem, const float* __restrict__ c0,
    const float* __restrict__ Wr)
{
    const int tid = threadIdx.x;
    const int blk = blockIdx.x;
    const int b = tid & 63;
    const int q = tid >> 6;
    const int u0 = blk * 2;

    __shared__ float2 Wc[512][4];     // 16 KB
    __shared__ float2 WrS[256][4];    // 8 KB
    __shared__ float As[2][32][65];   // double-buffered activation tile
    __shared__ float zs[64][8];
    __shared__ float hs[256];
    __shared__ float sc[32];
    __shared__ float al[32];

    for (int i = tid; i < 512 * 8; i += 256) {
        int k = i >> 3, c = i & 7;
        int j = (c >> 1) * 256 + u0 + (c & 1);
        ((float*)Wc)[k * 8 + c] = g_Wrc[(size_t)k * 1024 + j];
    }
    for (int i = tid; i < 256 * 8; i += 256) {
        int k = i >> 3, c = i & 7;
        int j = (c >> 1) * 256 + u0 + (c & 1);
        ((float*)WrS)[k * 8 + c] = Wr[(size_t)k * 1024 + j];
    }

    float creg = 0.0f;
    if (tid < 128)
        creg = c0[(tid & 63) * 256 + u0 + (tid >> 6)];
    __syncthreads();

    const int ab = tid >> 3;
    const int kf = (tid & 7) * 4;
    const int ab2 = (tid + 256) >> 3;
    const int kf2 = ((tid + 256) & 7) * 4;

    unsigned gen = 0;
    for (int t = 0; t < T_; t++) {
        const float* __restrict__ hprev = g_hbuf[t & 1];
        float* __restrict__ hnew = g_hbuf[1 - (t & 1)];

        const float* xwt = g_xw + (size_t)(t * 64 + b) * 1024;
        const int j0 = q * 256 + u0;
        float acc0 = xwt[j0];
        float acc1 = xwt[j0 + 1];

        // t==0: true attn_prev is ZERO, so use plain W_r over h only.
        const int kmax = (t == 0) ? 256 : 512;
        const float2 (*Wp)[4] = (t == 0) ? WrS : Wc;

        float4 va0, va1;
        {
            int kg1 = kf;
            const float4* s1 = (const float4*)((kg1 < 256)
                    ? (hprev + ab * 256 + kg1) : (g_ctx + ab * 256 + (kg1 - 256)));
            va0 = __ldcg(s1);
            int kg2 = kf2;
            const float4* s2 = (const float4*)((kg2 < 256)
                    ? (hprev + ab2 * 256 + kg2) : (g_ctx + ab2 * 256 + (kg2 - 256)));
            va1 = __ldcg(s2);
        }
        int buf = 0;
        for (int k0 = 0; k0 < kmax; k0 += 32) {
            As[buf][kf + 0][ab] = va0.x;
            As[buf][kf + 1][ab] = va0.y;
            As[buf][kf + 2][ab] = va0.z;
            As[buf][kf + 3][ab] = va0.w;
            As[buf][kf2 + 0][ab2] = va1.x;
            As[buf][kf2 + 1][ab2] = va1.y;
            As[buf][kf2 + 2][ab2] = va1.z;
            As[buf][kf2 + 3][ab2] = va1.w;
            if (k0 + 32 < kmax) {
                int kg1 = k0 + 32 + kf;
                const float4* s1 = (const float4*)((kg1 < 256)
                        ? (hprev + ab * 256 + kg1) : (g_ctx + ab * 256 + (kg1 - 256)));
                va0 = __ldcg(s1);
                int kg2 = k0 + 32 + kf2;
                const float4* s2 = (const float4*)((kg2 < 256)
                        ? (hprev + ab2 * 256 + kg2) : (g_ctx + ab2 * 256 + (kg2 - 256)));
                va1 = __ldcg(s2);
            }
            __syncthreads();
#pragma unroll
            for (int k = 0; k < 32; k++) {
                float a = As[buf][k][b];
                float2 w = Wp[k0 + k][q];
                acc0 += a * w.x;
                acc1 += a * w.y;
            }
            buf ^= 1;
        }
        __syncthreads();
        zs[b][q * 2 + 0] = acc0;
        zs[b][q * 2 + 1] = acc1;
        __syncthreads();
        if (tid < 128) {
            int du = tid >> 6;
            int bb = tid & 63;
            int u = u0 + du;
            float zi = zs[bb][0 + du];
            float zf = zs[bb][2 + du];
            float zg = zs[bb][4 + du];
            float zo = zs[bb][6 + du];
            float cn = sigm(zf) * creg + sigm(zi) * tanhf(zg);
            creg = cn;
            float h = sigm(zo) * tanhf(cn);
            hnew[bb * 256 + u] = h;
            g_hc[(size_t)(t * 64 + bb) * 512 + u] = h;
        }
        gen++;
        grid_barrier(gen * NBLK);

        // ---- phase B: attention for batch blk (blocks 0..63) ----
        if (blk < 64) {
            const int bb = blk;
            const int w = tid >> 5;
            const int l = tid & 31;
            hs[tid] = __ldcg(hnew + bb * 256 + tid);
            __syncthreads();
            for (int s = w; s < S_; s += 8) {
                const float* kp = g_keys + (size_t)(bb * S_ + s) * 256;
                float d = 0.0f;
#pragma unroll
                for (int i = 0; i < 8; i++) d += hs[l + 32 * i] * kp[l + 32 * i];
#pragma unroll
                for (int o = 16; o > 0; o >>= 1) d += __shfl_down_sync(0xffffffffu, d, o);
                if (l == 0) sc[s] = d;
            }
            __syncthreads();
            if (w == 0) {
                float v = (l < S_) ? sc[l] : -INFINITY;
                float mx = v;
#pragma unroll
                for (int o = 16; o > 0; o >>= 1) mx = fmaxf(mx, __shfl_xor_sync(0xffffffffu, mx, o));
                float e = (l < S_) ? expf(v - mx) : 0.0f;
                float sm = e;
#pragma unroll
                for (int o = 16; o > 0; o >>= 1) sm += __shfl_xor_sync(0xffffffffu, sm, o);
                if (l < S_) al[l] = e / sm;
            }
            __syncthreads();
            // fully-unrolled context accumulation: 31 independent L2 loads in flight
            const float* mp = mem + (size_t)bb * S_ * 256 + tid;
            float cx0 = 0.0f, cx1 = 0.0f, cx2 = 0.0f, cx3 = 0.0f;
#pragma unroll
            for (int s = 0; s < 28; s += 4) {
                cx0 += al[s + 0] * mp[(s + 0) * 256];
                cx1 += al[s + 1] * mp[(s + 1) * 256];
                cx2 += al[s + 2] * mp[(s + 2) * 256];
                cx3 += al[s + 3] * mp[(s + 3) * 256];
            }
            cx0 += al[28] * mp[28 * 256];
            cx1 += al[29] * mp[29 * 256];
            cx2 += al[30] * mp[30 * 256];
            float cx = (cx0 + cx1) + (cx2 + cx3);
            g_ctx[bb * 256 + tid] = cx;
            g_hc[(size_t)(t * 64 + bb) * 512 + 256 + tid] = cx;
            __syncthreads();
        }
        gen++;
        grid_barrier(gen * NBLK);
    }
}

// ---------------- A' conversion: attn f32 -> fp16 (hi only) ----------------
__global__ void k_convA(const float* __restrict__ attn) {
    const int m = blockIdx.x;
    const int k = threadIdx.x;
    g_Abf[(size_t)m * FC_K + k] = __float2half_rn(attn[(size_t)m * U_ + k]);
}

// ---------------- W' conversion: W_fc [256][32000] -> Wt [32000][256] = w_hi ----------------
__global__ void k_convW(const float* __restrict__ W) {
    __shared__ float tile[32][33];
    const int n0 = blockIdx.x * 32;
    const int k0 = blockIdx.y * 32;
    const int tx = threadIdx.x;
    const int ty = threadIdx.y;   // 0..7
#pragma unroll
    for (int i = 0; i < 4; i++) {
        int k = ty + i * 8;
        tile[k][tx] = W[(size_t)(k0 + k) * V_ + n0 + tx];
    }
    __syncthreads();
#pragma unroll
    for (int i = 0; i < 4; i++) {
        int nr = ty + i * 8;
        float v = tile[tx][nr];
        g_Wt[(size_t)(n0 + nr) * U_ + k0 + tx] = __float2half_rn(v);
    }
}

// ---------------- HMMA FC GEMM: out = Ahi(1920x256) @ Wt^T + b ----------------
#define TILE_B   10240                 // 128 rows * 80B
#define BUF_B    (2 * TILE_B)
__global__ __launch_bounds__(256, 2)
void fc_hmma_kernel(const __half* __restrict__ Abf,
                    const __half* __restrict__ Wt,
                    const float* __restrict__ bias,
                    float* __restrict__ out)
{
    extern __shared__ char smem[];
    const uint32_t sbase = smem_u32(smem);
    const int tid = threadIdx.x;
    const int wid = tid >> 5;
    const int lane = tid & 31;
    const int n0 = blockIdx.x * 128;
    const int m0 = blockIdx.y * 128;

    const int warp_m = (wid >> 2) * 64;
    const int warp_nq = wid & 3;

    const char* Agl = (const char*)Abf + (size_t)m0 * (FC_K * 2);   // 512 B rows
    const char* Bgl = (const char*)Wt + (size_t)n0 * (U_ * 2);      // 512 B rows

    float acc[4][4][4];
#pragma unroll
    for (int i = 0; i < 4; i++)
#pragma unroll
        for (int j = 0; j < 4; j++)
#pragma unroll
            for (int q = 0; q < 4; q++) acc[i][j][q] = 0.0f;

#define LOADST(S, P)                                                            \
    do {                                                                        \
        const uint32_t dA = sbase + (P) * BUF_B;                                \
        const uint32_t dB = dA + TILE_B;                                        \
        _Pragma("unroll")                                                       \
        for (int i_ = 0; i_ < 2; i_++) {                                        \
            int id_ = tid + i_ * 256;                                           \
            int r_ = id_ >> 2, c_ = id_ & 3;                                    \
            cp16(dA + r_ * 80 + c_ * 16,                                        \
                 Agl + (size_t)r_ * (FC_K * 2) + (S) * 64 + c_ * 16);           \
            cp16(dB + r_ * 80 + c_ * 16,                                        \
                 Bgl + (size_t)r_ * (U_ * 2) + (S) * 64 + c_ * 16);             \
        }                                                                       \
        asm volatile("cp.async.commit_group;" ::: "memory");                    \
    } while (0)

    LOADST(0, 0);
    LOADST(1, 1);

    const uint32_t a_off = (uint32_t)((warp_m + (lane & 15)) * 80 + (lane >> 4) * 16);
    const uint32_t b_off = (uint32_t)((warp_nq * 32 + (lane >> 4) * 8 + (lane & 7)) * 80 +
                                      ((lane >> 3) & 1) * 16);

    for (int s = 0; s < FC_NS; s++) {
        if (s < FC_NS - 1)
            asm volatile("cp.async.wait_group 1;" ::: "memory");
        else
            asm volatile("cp.async.wait_group 0;" ::: "memory");
        __syncthreads();

        if (s + 2 < FC_NS) {
            const int pb = (s + 2) % 3;
            LOADST(s + 2, pb);
        }

        const uint32_t sA = sbase + (uint32_t)(s % 3) * BUF_B;
        const uint32_t sB = sA + TILE_B;
#pragma unroll
        for (int ks = 0; ks < 2; ks++) {
            uint32_t af[4][4];
#pragma unroll
            for (int mt = 0; mt < 4; mt++)
                ldm_x4(af[mt], sA + a_off + mt * (16 * 80) + ks * 32);
            uint32_t bf[2][4];
#pragma unroll
            for (int g = 0; g < 2; g++)
                ldm_x4(bf[g], sB + b_off + g * (16 * 80) + ks * 32);
#pragma unroll
            for (int mt = 0; mt < 4; mt++)
#pragma unroll
                for (int nt = 0; nt < 4; nt++)
                    mma16816(acc[mt][nt], af[mt],
                             bf[nt >> 1][(nt & 1) * 2], bf[nt >> 1][(nt & 1) * 2 + 1]);
        }
    }

    // ---- epilogue: regs -> SMEM -> coalesced STG + bias; t-major -> b-major remap ----
    float* ep = (float*)smem;
    const int myhalf = warp_nq >> 1;
    const int colq = (warp_nq & 1) * 32;

#pragma unroll 1
    for (int h = 0; h < 2; h++) {
        __syncthreads();
        if (myhalf == h) {
#pragma unroll
            for (int mt = 0; mt < 4; mt++)
#pragma unroll
                for (int nt = 0; nt < 4; nt++) {
                    int row = warp_m + mt * 16 + (lane >> 2);
                    int col = colq + nt * 8 + (lane & 3) * 2;
                    ep[row * 68 + col]            = acc[mt][nt][0];
                    ep[row * 68 + col + 1]        = acc[mt][nt][1];
                    ep[(row + 8) * 68 + col]      = acc[mt][nt][2];
                    ep[(row + 8) * 68 + col + 1]  = acc[mt][nt][3];
                }
        }
        __syncthreads();
        const int gn0 = n0 + h * 64;
#pragma unroll
        for (int i = 0; i < 8; i++) {
            int idx = tid + i * 256;
            int row = idx >> 4;
            int q = idx & 15;
            int gm = m0 + row;                         // t-major: t*64+b
            int orow = (gm & 63) * T_ + (gm >> 6);     // b*30+t
            float4 v = *(const float4*)&ep[row * 68 + q * 4];
            float4 bb = *(const float4*)&bias[gn0 + q * 4];
            v.x += bb.x; v.y += bb.y; v.z += bb.z; v.w += bb.w;
            *(float4*)&out[(size_t)orow * V_ + gn0 + q * 4] = v;
        }
    }
#undef LOADST
}

// ---------------- launcher ----------------
extern "C" void kernel_launch(void* const* d_in, const int* in_sizes, int n_in,
                              void* d_out, int out_size)
{
    const void*  inputs   = d_in[0];
    const float* memory   = (const float*)d_in[1];
    const float* sample_h = (const float*)d_in[2];
    const float* sample_c = (const float*)d_in[3];
    const float* emb      = (const float*)d_in[4];
    const float* W_k      = (const float*)d_in[5];
    const float* W_r      = (const float*)d_in[6];
    const float* b_lstm   = (const float*)d_in[7];
    const float* W_mem    = (const float*)d_in[8];
    const float* W_attn   = (const float*)d_in[9];
    const float* W_fc     = (const float*)d_in[10];
    const float* b_fc     = (const float*)d_in[11];
    float* out = (float*)d_out;

    float *p_attn;
    __half *p_Abf, *p_Wt;
    cudaGetSymbolAddress((void**)&p_attn, g_attn);
    cudaGetSymbolAddress((void**)&p_Abf, g_Abf);
    cudaGetSymbolAddress((void**)&p_Wt, g_Wt);

    cudaFuncSetAttribute(fc_hmma_kernel, cudaFuncAttributeMaxDynamicSharedMemorySize, 3 * BUF_B);

    // 0: gather embeddings + init state
    k_gather<<<B_ * T_, E_>>>(inputs, emb, sample_h);
    // 1: fused pre-GEMMs (keys | xw | Wcomb+W_r), 732 CTAs fill the machine
    k_multigemm<<<124 + 480 + 128, 256>>>(memory, W_mem, W_k, b_lstm, W_attn, W_r);
    // 2: W' fp16 transpose
    k_convW<<<dim3(V_ / 32, U_ / 32), dim3(32, 8)>>>(W_fc);
    // 3: whole recurrence, ONE persistent launch (t=0 uses W_r path)
    recur_kernel<<<NBLK, 256>>>(memory, sample_c, W_r);
    // 4: attn_seq = hc_seq @ W_attn (t-major rows)
    k_sgemm_attn<<<dim3(4, 30), 256>>>(W_attn);
    // 5: fp16 conversion of A
    k_convA<<<B_ * T_, 256>>>(p_attn);
    // 6: FC on tensor cores, single-term fp16 K=256
    fc_hmma_kernel<<<dim3(V_ / 128, 15), 256, 3 * BUF_B>>>(p_Abf, p_Wt, b_fc, out);
}